// round 15
// baseline (speedup 1.0000x reference)
#include <cuda_runtime.h>
#include <cuda_fp16.h>
#include <cstdint>

// ---------------------------------------------------------------------------
// PopulationGNN: 4-layer GCN, N=50000, IN_DIM=2000, HID=64, E=1.6M
// CSR build once (packed src+weight), then per layer:
// TF32 mma GEMM (cp.async.cg 3-stage, raw-bits fast tf32, fp16 out)
// -> warp-per-node gather (packed int4 edges, fp16 AGG out)
// -> BN stats+finalize (256-block ticket, fp16 AGG in)
// -> norm/relu/res/emb fused (fp16 AGG in, fp32 OUT/EMB out).
// ---------------------------------------------------------------------------

#define HID 64
#define MAXN 50048
#define MAXE 1600256
#define STATS_BLOCKS 256
#define SBS 256
#define MAXSB 256

__device__ __align__(16) __half g_XWH[MAXN * HID];   // fp16 XW (gather input)
__device__ __align__(16) __half g_AGGH[MAXN * HID];  // fp16 AGG (gather output)
__device__ __align__(16) float g_OUT0[MAXN * HID];
__device__ __align__(16) float g_OUT1[MAXN * HID];
__device__ int   g_DEGI[MAXN];
__device__ float g_DINV[MAXN];
__device__ __align__(16) int2 g_EPK[MAXE];           // packed {src, weight-bits}
__device__ int   g_ROWPTR[MAXN + 1];
__device__ int   g_CUR[MAXN];
__device__ int   g_ROWEXC[MAXN];
__device__ int   g_BTOT[MAXSB];
__device__ int   g_BOFF[MAXSB];
__device__ int   g_IS32;
__device__ unsigned int g_TICKET;
__device__ __align__(16) float g_PART[STATS_BLOCKS * 128];
__device__ __align__(16) float g_SS[132];

// ---------------------------------------------------------------------------
// Setup: fused init+detect, then CSR build (dinv folded into scan1)
// ---------------------------------------------------------------------------

__global__ void init_detect_kernel(const int* __restrict__ words, int n, int E) {
    int i = blockIdx.x * blockDim.x + threadIdx.x;
    if (i < n) g_DEGI[i] = 0;
    if (i == 0) { g_IS32 = 0; g_TICKET = 0; }
    int idx = 2 * i + 1;
    if (idx < E && words[idx] != 0)
        atomicOr(&g_IS32, 1);
}

__device__ __forceinline__ void decode_edge(const int* __restrict__ words, int E, int e,
                                            int& s, int& d) {
    if (g_IS32) {
        s = words[e];
        d = words[E + e];
    } else {
        s = words[2 * e];
        d = words[2 * E + 2 * e];
    }
}

__global__ void count_kernel(const int* __restrict__ words, int E) {
    int e = blockIdx.x * blockDim.x + threadIdx.x;
    if (e < E) {
        int s, d;
        decode_edge(words, E, e, s, d);
        atomicAdd(&g_DEGI[d], 1);
    }
}

__global__ void scan1_kernel(int n) {
    __shared__ int sm[SBS];
    int t = threadIdx.x;
    int i = blockIdx.x * SBS + t;
    int v = (i < n) ? g_DEGI[i] : 0;
    if (i < n) g_DINV[i] = rsqrtf((float)v + 1.0f);
    sm[t] = v;
    __syncthreads();
#pragma unroll
    for (int off = 1; off < SBS; off <<= 1) {
        int y = (t >= off) ? sm[t - off] : 0;
        __syncthreads();
        sm[t] += y;
        __syncthreads();
    }
    if (i < n) g_ROWEXC[i] = sm[t] - v;
    if (t == SBS - 1) g_BTOT[blockIdx.x] = sm[t];
}

__global__ void scan2_kernel(int nb) {
    __shared__ int sm[SBS];
    int t = threadIdx.x;
    int v = (t < nb) ? g_BTOT[t] : 0;
    sm[t] = v;
    __syncthreads();
#pragma unroll
    for (int off = 1; off < SBS; off <<= 1) {
        int y = (t >= off) ? sm[t - off] : 0;
        __syncthreads();
        sm[t] += y;
        __syncthreads();
    }
    if (t < nb) g_BOFF[t] = sm[t] - v;
}

__global__ void scan3_kernel(int n, int E) {
    int i = blockIdx.x * blockDim.x + threadIdx.x;
    if (i < n) {
        int r = g_ROWEXC[i] + g_BOFF[i / SBS];
        g_ROWPTR[i] = r;
        g_CUR[i] = r;
    }
    if (i == 0) g_ROWPTR[n] = E;
}

__global__ void fill_kernel(const int* __restrict__ words, int E) {
    int e = blockIdx.x * blockDim.x + threadIdx.x;
    if (e < E) {
        int s, d;
        decode_edge(words, E, e, s, d);
        int pos = atomicAdd(&g_CUR[d], 1);
        float w = g_DINV[s] * g_DINV[d];
        g_EPK[pos] = make_int2(s, __float_as_int(w));
    }
}

// ---------------------------------------------------------------------------
// TF32 GEMM, cp.async.cg 3-stage pipeline, raw-bits fast-tf32 fragments.
// A[M,K] @ W[K,64] -> g_XWH (fp16). (UNCHANGED from R13 — protected.)
// ---------------------------------------------------------------------------

#define NSTAGE 3

__device__ __forceinline__ void mma_tf32(float& c0, float& c1, float& c2, float& c3,
                                         uint32_t a0, uint32_t a1, uint32_t a2, uint32_t a3,
                                         uint32_t b0, uint32_t b1) {
    asm volatile(
        "mma.sync.aligned.m16n8k8.row.col.f32.tf32.tf32.f32 "
        "{%0,%1,%2,%3}, {%4,%5,%6,%7}, {%8,%9}, {%0,%1,%2,%3};"
        : "+f"(c0), "+f"(c1), "+f"(c2), "+f"(c3)
        : "r"(a0), "r"(a1), "r"(a2), "r"(a3), "r"(b0), "r"(b1));
}

__device__ __forceinline__ void cp16(uint32_t smem_addr, const float* gptr) {
    asm volatile("cp.async.cg.shared.global [%0], [%1], 16;"
                 :: "r"(smem_addr), "l"(gptr));
}

__global__ void __launch_bounds__(256, 3)
gemm_tf32_kernel(const float* __restrict__ feat, int src_sel,
                 const float* __restrict__ W, int M, int K) {
    __shared__ uint32_t As[NSTAGE][128][20];
    __shared__ uint32_t Bs[NSTAGE][16][72];

    const float* A = (src_sel == 0) ? feat : (src_sel == 1 ? g_OUT0 : g_OUT1);

    int t = threadIdx.x;
    int m0 = blockIdx.x * 128;
    int warp = t >> 5;
    int lane = t & 31;
    int wm = (warp >> 1) * 32;
    int wn = (warp & 1) * 32;
    int fr = lane >> 2;
    int fc = lane & 3;

    float acc[2][4][4];
#pragma unroll
    for (int i = 0; i < 2; i++)
#pragma unroll
        for (int j = 0; j < 4; j++)
#pragma unroll
            for (int q = 0; q < 4; q++) acc[i][j][q] = 0.0f;

    int arow[2], akc[2];
#pragma unroll
    for (int i = 0; i < 2; i++) {
        int idx = t + i * 256;
        arow[i] = idx >> 2;
        akc[i] = (idx & 3) * 4;
    }
    int bkr = t >> 4;
    int bnc = (t & 15) * 4;

    int grow[2];
#pragma unroll
    for (int i = 0; i < 2; i++) {
        int r = m0 + arow[i];
        grow[i] = (r < M) ? r : (M - 1);
    }

    uint32_t sA[2], sB;
#pragma unroll
    for (int i = 0; i < 2; i++)
        sA[i] = (uint32_t)__cvta_generic_to_shared(&As[0][arow[i]][akc[i]]);
    sB = (uint32_t)__cvta_generic_to_shared(&Bs[0][bkr][bnc]);
    const uint32_t stA = sizeof(As[0]);
    const uint32_t stB = sizeof(Bs[0]);

    auto prefetch = [&](int tile) {
        int k0 = tile << 4;
        int stg = tile % NSTAGE;
#pragma unroll
        for (int i = 0; i < 2; i++)
            cp16(sA[i] + stg * stA, &A[(size_t)grow[i] * K + k0 + akc[i]]);
        cp16(sB + stg * stB, &W[(size_t)(k0 + bkr) * HID + bnc]);
    };

    int T = K >> 4;

    prefetch(0);
    asm volatile("cp.async.commit_group;");
    prefetch(1);
    asm volatile("cp.async.commit_group;");

    for (int tt = 0; tt < T; ++tt) {
        asm volatile("cp.async.wait_group 1;");
        __syncthreads();
        if (tt + 2 < T) prefetch(tt + 2);
        asm volatile("cp.async.commit_group;");

        int buf = tt % NSTAGE;
#pragma unroll
        for (int kk = 0; kk < 16; kk += 8) {
            uint32_t af[2][4];
#pragma unroll
            for (int i = 0; i < 2; i++) {
                int rb = wm + i * 16 + fr;
                af[i][0] = As[buf][rb][kk + fc];
                af[i][1] = As[buf][rb + 8][kk + fc];
                af[i][2] = As[buf][rb][kk + fc + 4];
                af[i][3] = As[buf][rb + 8][kk + fc + 4];
            }
            uint32_t bf[4][2];
#pragma unroll
            for (int j = 0; j < 4; j++) {
                int nb = wn + j * 8 + fr;
                bf[j][0] = Bs[buf][kk + fc][nb];
                bf[j][1] = Bs[buf][kk + fc + 4][nb];
            }
#pragma unroll
            for (int i = 0; i < 2; i++)
#pragma unroll
                for (int j = 0; j < 4; j++)
                    mma_tf32(acc[i][j][0], acc[i][j][1], acc[i][j][2], acc[i][j][3],
                             af[i][0], af[i][1], af[i][2], af[i][3],
                             bf[j][0], bf[j][1]);
        }
    }

#pragma unroll
    for (int i = 0; i < 2; i++) {
#pragma unroll
        for (int j = 0; j < 4; j++) {
            int row = m0 + wm + i * 16 + fr;
            int col = wn + j * 8 + fc * 2;
            if (row < M)
                *reinterpret_cast<__half2*>(&g_XWH[(size_t)row * HID + col]) =
                    __floats2half2_rn(acc[i][j][0], acc[i][j][1]);
            if (row + 8 < M)
                *reinterpret_cast<__half2*>(&g_XWH[(size_t)(row + 8) * HID + col]) =
                    __floats2half2_rn(acc[i][j][2], acc[i][j][3]);
        }
    }
}

// ---------------------------------------------------------------------------
// Gather: warp per node (R13 shape), packed int4 edge loads, fp16 AGG output.
// Lane owns channels {2l, 2l+1}. AGG[v] = sn*XW[v] + sum w_e * XW[src_e].
// ---------------------------------------------------------------------------

__global__ void gather_kernel(int N) {
    int gid = blockIdx.x * blockDim.x + threadIdx.x;
    int v = gid >> 5;
    int lane = gid & 31;
    if (v >= N) return;

    const __half2* XH2 = reinterpret_cast<const __half2*>(g_XWH);

    int beg = g_ROWPTR[v];
    int end = g_ROWPTR[v + 1];
    float dn = g_DINV[v];
    float sn = dn * dn;

    float2 self = __half22float2(XH2[v * 32 + lane]);
    float a0 = self.x * sn;
    float a1 = self.y * sn;

    int j = beg;
    if ((j & 1) && j < end) {
        int2 p = g_EPK[j];
        float2 x = __half22float2(XH2[p.x * 32 + lane]);
        float w = __int_as_float(p.y);
        a0 = fmaf(w, x.x, a0);
        a1 = fmaf(w, x.y, a1);
        j++;
    }
    for (; j + 3 < end; j += 4) {
        int4 pA = *reinterpret_cast<const int4*>(&g_EPK[j]);
        int4 pB = *reinterpret_cast<const int4*>(&g_EPK[j + 2]);
        float w0 = __int_as_float(pA.y);
        float w1 = __int_as_float(pA.w);
        float w2 = __int_as_float(pB.y);
        float w3 = __int_as_float(pB.w);
        float2 x0 = __half22float2(XH2[pA.x * 32 + lane]);
        float2 x1 = __half22float2(XH2[pA.z * 32 + lane]);
        float2 x2 = __half22float2(XH2[pB.x * 32 + lane]);
        float2 x3 = __half22float2(XH2[pB.z * 32 + lane]);
        a0 = fmaf(w0, x0.x, a0);
        a1 = fmaf(w0, x0.y, a1);
        a0 = fmaf(w1, x1.x, a0);
        a1 = fmaf(w1, x1.y, a1);
        a0 = fmaf(w2, x2.x, a0);
        a1 = fmaf(w2, x2.y, a1);
        a0 = fmaf(w3, x3.x, a0);
        a1 = fmaf(w3, x3.y, a1);
    }
    for (; j < end; ++j) {
        int2 p = g_EPK[j];
        float2 x = __half22float2(XH2[p.x * 32 + lane]);
        float w = __int_as_float(p.y);
        a0 = fmaf(w, x.x, a0);
        a1 = fmaf(w, x.y, a1);
    }

    *reinterpret_cast<__half2*>(&g_AGGH[v * HID + 2 * lane]) =
        __floats2half2_rn(a0, a1);
}

// ---------------------------------------------------------------------------
// BN stats + finalize (256 blocks, deterministic last-block ticket).
// AGG is fp16: each thread reads uint4 (8 channels); thread's channel group
// is (i & 7)*8 (stride 65536 is a multiple of 8, so group is loop-invariant).
// ---------------------------------------------------------------------------

__global__ void bn_stats_fin_kernel(const float* __restrict__ gamma,
                                    const float* __restrict__ beta,
                                    const float* __restrict__ lw,
                                    int layer, int L, int N) {
    __shared__ float ssum[256][8];
    __shared__ float ssq[256][8];
    __shared__ unsigned int sIsLast;
    const uint4* AGGH4 = reinterpret_cast<const uint4*>(g_AGGH);
    int t = threadIdx.x;
    int stride = gridDim.x * blockDim.x;     // 65536, multiple of 8
    int total = N * 8;                       // uint4 count

    float s[8], q[8];
#pragma unroll
    for (int k = 0; k < 8; k++) { s[k] = 0.f; q[k] = 0.f; }

    for (int i = blockIdx.x * blockDim.x + t; i < total; i += stride) {
        uint4 u = AGGH4[i];
        const __half2* hp = reinterpret_cast<const __half2*>(&u);
#pragma unroll
        for (int k = 0; k < 4; k++) {
            float2 f = __half22float2(hp[k]);
            s[2 * k]     += f.x;
            s[2 * k + 1] += f.y;
            q[2 * k]     = fmaf(f.x, f.x, q[2 * k]);
            q[2 * k + 1] = fmaf(f.y, f.y, q[2 * k + 1]);
        }
    }
#pragma unroll
    for (int k = 0; k < 8; k++) { ssum[t][k] = s[k]; ssq[t][k] = q[k]; }
    __syncthreads();
    for (int off = 128; off >= 8; off >>= 1) {
        if (t < off) {
#pragma unroll
            for (int k = 0; k < 8; k++) {
                ssum[t][k] += ssum[t + off][k];
                ssq[t][k]  += ssq[t + off][k];
            }
        }
        __syncthreads();
    }
    // Rows 0..7: row r holds totals for channels r*8..r*8+7.
    if (t < 8) {
#pragma unroll
        for (int k = 0; k < 8; k++) {
            g_PART[blockIdx.x * 128 + t * 8 + k] = ssum[t][k];
            g_PART[blockIdx.x * 128 + 64 + t * 8 + k] = ssq[t][k];
        }
    }
    __threadfence();
    __syncthreads();
    if (t == 0)
        sIsLast = (atomicAdd(&g_TICKET, 1u) == (unsigned)gridDim.x - 1u) ? 1u : 0u;
    __syncthreads();
    if (!sIsLast) return;

    if (t == 0) g_TICKET = 0;
    int c = t & 63;
    int g0 = t >> 6;
    float fs = 0.f, fq = 0.f;
    for (int g = g0; g < STATS_BLOCKS; g += 4) {
        fs += g_PART[g * 128 + c];
        fq += g_PART[g * 128 + 64 + c];
    }
    __syncthreads();
    float* r_s = reinterpret_cast<float*>(ssum);
    float* r_q = reinterpret_cast<float*>(ssq);
    r_s[t] = fs;
    r_q[t] = fq;
    __syncthreads();
    if (t < 128) { r_s[t] += r_s[t + 128]; r_q[t] += r_q[t + 128]; }
    __syncthreads();
    if (t < 64) {
        float S = r_s[t] + r_s[t + 64];
        float Q = r_q[t] + r_q[t + 64];
        float invN = 1.0f / (float)N;
        float mean = S * invN;
        float var = Q * invN - mean * mean;
        float inv = rsqrtf(var + 1e-5f);
        float sc = gamma[layer * HID + c] * inv;
        g_SS[c] = sc;
        g_SS[64 + c] = beta[layer * HID + c] - mean * sc;
    }
    if (t == 0) {
        float se = 0.f;
        for (int j = 0; j < L; j++) se += expf(lw[j]);
        g_SS[128] = expf(lw[layer]) / se;
    }
}

// ---------------------------------------------------------------------------
// Normalize + ReLU + residual + softmax-weighted emb accumulation.
// fp16 AGG in (uint4 = 8 channels/thread), fp32 OUT/EMB out.
// ---------------------------------------------------------------------------

__global__ void bn_norm_kernel(float4* __restrict__ EMB4, int N, int layer, int store_out) {
    const uint4* AGGH4  = reinterpret_cast<const uint4*>(g_AGGH);
    const float4* PREV4 = reinterpret_cast<const float4*>((layer & 1) ? g_OUT0 : g_OUT1);
    float4* OUT4        = reinterpret_cast<float4*>((layer & 1) ? g_OUT1 : g_OUT0);

    int t0 = blockIdx.x * blockDim.x + threadIdx.x;
    int c8 = (t0 & 7) * 8;
    float4 sc0 = *reinterpret_cast<const float4*>(&g_SS[c8]);
    float4 sc1 = *reinterpret_cast<const float4*>(&g_SS[c8 + 4]);
    float4 sh0 = *reinterpret_cast<const float4*>(&g_SS[64 + c8]);
    float4 sh1 = *reinterpret_cast<const float4*>(&g_SS[64 + c8 + 4]);
    float w = g_SS[128];
    int total = N * 8;                       // uint4 count
    int stride = gridDim.x * blockDim.x;     // 131072, multiple of 8
    for (int i = t0; i < total; i += stride) {
        uint4 u = AGGH4[i];
        const __half2* hp = reinterpret_cast<const __half2*>(&u);
        float2 f0 = __half22float2(hp[0]);
        float2 f1 = __half22float2(hp[1]);
        float2 f2 = __half22float2(hp[2]);
        float2 f3 = __half22float2(hp[3]);

        float4 oA, oB;
        oA.x = fmaxf(fmaf(f0.x, sc0.x, sh0.x), 0.f);
        oA.y = fmaxf(fmaf(f0.y, sc0.y, sh0.y), 0.f);
        oA.z = fmaxf(fmaf(f1.x, sc0.z, sh0.z), 0.f);
        oA.w = fmaxf(fmaf(f1.y, sc0.w, sh0.w), 0.f);
        oB.x = fmaxf(fmaf(f2.x, sc1.x, sh1.x), 0.f);
        oB.y = fmaxf(fmaf(f2.y, sc1.y, sh1.y), 0.f);
        oB.z = fmaxf(fmaf(f3.x, sc1.z, sh1.z), 0.f);
        oB.w = fmaxf(fmaf(f3.y, sc1.w, sh1.w), 0.f);

        if (layer > 0) {
            float4 pA = PREV4[2 * i];
            float4 pB = PREV4[2 * i + 1];
            oA.x = fmaf(0.7f, pA.x, oA.x);
            oA.y = fmaf(0.7f, pA.y, oA.y);
            oA.z = fmaf(0.7f, pA.z, oA.z);
            oA.w = fmaf(0.7f, pA.w, oA.w);
            oB.x = fmaf(0.7f, pB.x, oB.x);
            oB.y = fmaf(0.7f, pB.y, oB.y);
            oB.z = fmaf(0.7f, pB.z, oB.z);
            oB.w = fmaf(0.7f, pB.w, oB.w);
        }
        if (store_out) {
            OUT4[2 * i] = oA;
            OUT4[2 * i + 1] = oB;
        }
        if (layer == 0) {
            EMB4[2 * i] = make_float4(w * oA.x, w * oA.y, w * oA.z, w * oA.w);
            EMB4[2 * i + 1] = make_float4(w * oB.x, w * oB.y, w * oB.z, w * oB.w);
        } else {
            float4 eA = EMB4[2 * i];
            float4 eB = EMB4[2 * i + 1];
            eA.x = fmaf(w, oA.x, eA.x);
            eA.y = fmaf(w, oA.y, eA.y);
            eA.z = fmaf(w, oA.z, eA.z);
            eA.w = fmaf(w, oA.w, eA.w);
            eB.x = fmaf(w, oB.x, eB.x);
            eB.y = fmaf(w, oB.y, eB.y);
            eB.z = fmaf(w, oB.z, eB.z);
            eB.w = fmaf(w, oB.w, eB.w);
            EMB4[2 * i] = eA;
            EMB4[2 * i + 1] = eB;
        }
    }
}

// ---------------------------------------------------------------------------
// Host launcher — kernel launches only; layer-0 GEMM at launch #4 (profiled).
// ---------------------------------------------------------------------------

extern "C" void kernel_launch(void* const* d_in, const int* in_sizes, int n_in,
                              void* d_out, int out_size) {
    const float* feat  = (const float*)d_in[0];
    const int* ewords  = (const int*)d_in[1];
    const float* W0    = (const float*)d_in[2];
    const float* Wh    = (const float*)d_in[4];
    const float* gamma = (const float*)d_in[6];
    const float* beta  = (const float*)d_in[7];
    const float* lw    = (const float*)d_in[8];
    float* out         = (float*)d_out;

    int hid    = in_sizes[3];
    int in_dim = in_sizes[2] / hid;
    int N      = in_sizes[0] / in_dim;
    int E      = in_sizes[1] / 2;
    int L      = in_sizes[8];

    int nb = (N + SBS - 1) / SBS;
    int gemm_blocks = (N + 127) / 128;
    int gather_blocks = (N * 32 + 255) / 256;   // warp per node

    init_detect_kernel<<<(N + 255) / 256, 256>>>(ewords, N, E);              // 1
    count_kernel<<<(E + 255) / 256, 256>>>(ewords, E);                       // 2
    scan1_kernel<<<nb, SBS>>>(N);                                            // 3 (+dinv)
    gemm_tf32_kernel<<<gemm_blocks, 256>>>(feat, 0, W0, N, in_dim);          // 4 (profiled)
    scan2_kernel<<<1, SBS>>>(nb);                                            // 5
    scan3_kernel<<<(N + 255) / 256, 256>>>(N, E);                            // 6
    fill_kernel<<<(E + 255) / 256, 256>>>(ewords, E);                        // 7

    for (int layer = 0; layer < L; layer++) {
        if (layer > 0) {
            int src_sel = ((layer - 1) & 1) ? 2 : 1;
            const float* W = Wh + (size_t)(layer - 1) * hid * hid;
            gemm_tf32_kernel<<<gemm_blocks, 256>>>(feat, src_sel, W, N, hid);
        }
        gather_kernel<<<gather_blocks, 256>>>(N);
        bn_stats_fin_kernel<<<STATS_BLOCKS, 256>>>(gamma, beta, lw, layer, L, N);
        bn_norm_kernel<<<512, 256>>>((float4*)out, N, layer, layer < L - 1 ? 1 : 0);
    }
}

// round 16
// speedup vs baseline: 1.0655x; 1.0655x over previous
#include <cuda_runtime.h>
#include <cuda_fp16.h>
#include <cstdint>

// ---------------------------------------------------------------------------
// PopulationGNN: 4-layer GCN, N=50000, IN_DIM=2000, HID=64, E=1.6M
// CSR build once (packed src+weight), then per layer:
// TF32 mma GEMM (cp.async.cg, templated NSTAGE 4(pref)/3(fallback), raw-bits
// fast tf32, fp16 out) -> warp-per-node gather (packed int4 edges, fp32 AGG)
// -> BN stats+finalize (256-block ticket) -> norm/relu/res/emb fused (fp32).
// ---------------------------------------------------------------------------

#define HID 64
#define MAXN 50048
#define MAXE 1600256
#define STATS_BLOCKS 256
#define SBS 256
#define MAXSB 256

__device__ __align__(16) __half g_XWH[MAXN * HID];   // fp16 XW (gather input)
__device__ __align__(16) float g_AGG[MAXN * HID];
__device__ __align__(16) float g_OUT0[MAXN * HID];
__device__ __align__(16) float g_OUT1[MAXN * HID];
__device__ int   g_DEGI[MAXN];
__device__ float g_DINV[MAXN];
__device__ __align__(16) int2 g_EPK[MAXE];           // packed {src, weight-bits}
__device__ int   g_ROWPTR[MAXN + 1];
__device__ int   g_CUR[MAXN];
__device__ int   g_ROWEXC[MAXN];
__device__ int   g_BTOT[MAXSB];
__device__ int   g_BOFF[MAXSB];
__device__ int   g_IS32;
__device__ unsigned int g_TICKET;
__device__ __align__(16) float g_PART[STATS_BLOCKS * 128];
__device__ __align__(16) float g_SS[132];

// ---------------------------------------------------------------------------
// Setup: fused init+detect, then CSR build (dinv folded into scan1)
// ---------------------------------------------------------------------------

__global__ void init_detect_kernel(const int* __restrict__ words, int n, int E) {
    int i = blockIdx.x * blockDim.x + threadIdx.x;
    if (i < n) g_DEGI[i] = 0;
    if (i == 0) { g_IS32 = 0; g_TICKET = 0; }
    int idx = 2 * i + 1;
    if (idx < E && words[idx] != 0)
        atomicOr(&g_IS32, 1);
}

__device__ __forceinline__ void decode_edge(const int* __restrict__ words, int E, int e,
                                            int& s, int& d) {
    if (g_IS32) {
        s = words[e];
        d = words[E + e];
    } else {
        s = words[2 * e];
        d = words[2 * E + 2 * e];
    }
}

__global__ void count_kernel(const int* __restrict__ words, int E) {
    int e = blockIdx.x * blockDim.x + threadIdx.x;
    if (e < E) {
        int s, d;
        decode_edge(words, E, e, s, d);
        atomicAdd(&g_DEGI[d], 1);
    }
}

__global__ void scan1_kernel(int n) {
    __shared__ int sm[SBS];
    int t = threadIdx.x;
    int i = blockIdx.x * SBS + t;
    int v = (i < n) ? g_DEGI[i] : 0;
    if (i < n) g_DINV[i] = rsqrtf((float)v + 1.0f);
    sm[t] = v;
    __syncthreads();
#pragma unroll
    for (int off = 1; off < SBS; off <<= 1) {
        int y = (t >= off) ? sm[t - off] : 0;
        __syncthreads();
        sm[t] += y;
        __syncthreads();
    }
    if (i < n) g_ROWEXC[i] = sm[t] - v;
    if (t == SBS - 1) g_BTOT[blockIdx.x] = sm[t];
}

__global__ void scan2_kernel(int nb) {
    __shared__ int sm[SBS];
    int t = threadIdx.x;
    int v = (t < nb) ? g_BTOT[t] : 0;
    sm[t] = v;
    __syncthreads();
#pragma unroll
    for (int off = 1; off < SBS; off <<= 1) {
        int y = (t >= off) ? sm[t - off] : 0;
        __syncthreads();
        sm[t] += y;
        __syncthreads();
    }
    if (t < nb) g_BOFF[t] = sm[t] - v;
}

__global__ void scan3_kernel(int n, int E) {
    int i = blockIdx.x * blockDim.x + threadIdx.x;
    if (i < n) {
        int r = g_ROWEXC[i] + g_BOFF[i / SBS];
        g_ROWPTR[i] = r;
        g_CUR[i] = r;
    }
    if (i == 0) g_ROWPTR[n] = E;
}

__global__ void fill_kernel(const int* __restrict__ words, int E) {
    int e = blockIdx.x * blockDim.x + threadIdx.x;
    if (e < E) {
        int s, d;
        decode_edge(words, E, e, s, d);
        int pos = atomicAdd(&g_CUR[d], 1);
        float w = g_DINV[s] * g_DINV[d];
        g_EPK[pos] = make_int2(s, __float_as_int(w));
    }
}

// ---------------------------------------------------------------------------
// TF32 GEMM, cp.async.cg pipeline, raw-bits fast-tf32, templated NSTAGE.
// A[M,K] @ W[K,64] -> g_XWH (fp16). BM=128, BN=64, BK=16, 256 thr, 8 warps,
// warp tile 32x32 via m16n8k8. Dynamic smem: NS*(128*20 + 16*72) u32 words.
// ---------------------------------------------------------------------------

#define A_ST 2560   // 128*20 u32 per stage
#define B_ST 1152   // 16*72 u32 per stage

__device__ __forceinline__ void mma_tf32(float& c0, float& c1, float& c2, float& c3,
                                         uint32_t a0, uint32_t a1, uint32_t a2, uint32_t a3,
                                         uint32_t b0, uint32_t b1) {
    asm volatile(
        "mma.sync.aligned.m16n8k8.row.col.f32.tf32.tf32.f32 "
        "{%0,%1,%2,%3}, {%4,%5,%6,%7}, {%8,%9}, {%0,%1,%2,%3};"
        : "+f"(c0), "+f"(c1), "+f"(c2), "+f"(c3)
        : "r"(a0), "r"(a1), "r"(a2), "r"(a3), "r"(b0), "r"(b1));
}

__device__ __forceinline__ void cp16(uint32_t smem_addr, const float* gptr) {
    asm volatile("cp.async.cg.shared.global [%0], [%1], 16;"
                 :: "r"(smem_addr), "l"(gptr));
}

template<int NS>
__global__ void __launch_bounds__(256, 3)
gemm_tf32_kernel(const float* __restrict__ feat, int src_sel,
                 const float* __restrict__ W, int M, int K) {
    extern __shared__ uint32_t smem[];
    uint32_t* As = smem;                 // [NS][128][20]
    uint32_t* Bs = smem + NS * A_ST;     // [NS][16][72]

    const float* A = (src_sel == 0) ? feat : (src_sel == 1 ? g_OUT0 : g_OUT1);

    int t = threadIdx.x;
    int m0 = blockIdx.x * 128;
    int warp = t >> 5;
    int lane = t & 31;
    int wm = (warp >> 1) * 32;
    int wn = (warp & 1) * 32;
    int fr = lane >> 2;
    int fc = lane & 3;

    float acc[2][4][4];
#pragma unroll
    for (int i = 0; i < 2; i++)
#pragma unroll
        for (int j = 0; j < 4; j++)
#pragma unroll
            for (int q = 0; q < 4; q++) acc[i][j][q] = 0.0f;

    int arow[2], akc[2];
#pragma unroll
    for (int i = 0; i < 2; i++) {
        int idx = t + i * 256;
        arow[i] = idx >> 2;
        akc[i] = (idx & 3) * 4;
    }
    int bkr = t >> 4;
    int bnc = (t & 15) * 4;

    int grow[2];
#pragma unroll
    for (int i = 0; i < 2; i++) {
        int r = m0 + arow[i];
        grow[i] = (r < M) ? r : (M - 1);
    }

    uint32_t sA[2], sB;
#pragma unroll
    for (int i = 0; i < 2; i++)
        sA[i] = (uint32_t)__cvta_generic_to_shared(&As[arow[i] * 20 + akc[i]]);
    sB = (uint32_t)__cvta_generic_to_shared(&Bs[bkr * 72 + bnc]);
    const uint32_t stA = A_ST * 4;
    const uint32_t stB = B_ST * 4;

    auto prefetch = [&](int tile) {
        int k0 = tile << 4;
        int stg = tile % NS;
#pragma unroll
        for (int i = 0; i < 2; i++)
            cp16(sA[i] + stg * stA, &A[(size_t)grow[i] * K + k0 + akc[i]]);
        cp16(sB + stg * stB, &W[(size_t)(k0 + bkr) * HID + bnc]);
    };

    int T = K >> 4;

#pragma unroll
    for (int p = 0; p < NS - 1; ++p) {
        if (p < T) prefetch(p);
        asm volatile("cp.async.commit_group;");
    }

    for (int tt = 0; tt < T; ++tt) {
        asm volatile("cp.async.wait_group %0;" :: "n"(NS - 2));
        __syncthreads();
        if (tt + NS - 1 < T) prefetch(tt + NS - 1);
        asm volatile("cp.async.commit_group;");

        int buf = tt % NS;
        const uint32_t* Ab = &As[buf * A_ST];
        const uint32_t* Bb = &Bs[buf * B_ST];
#pragma unroll
        for (int kk = 0; kk < 16; kk += 8) {
            uint32_t af[2][4];
#pragma unroll
            for (int i = 0; i < 2; i++) {
                int rb = wm + i * 16 + fr;
                af[i][0] = Ab[rb * 20 + kk + fc];
                af[i][1] = Ab[(rb + 8) * 20 + kk + fc];
                af[i][2] = Ab[rb * 20 + kk + fc + 4];
                af[i][3] = Ab[(rb + 8) * 20 + kk + fc + 4];
            }
            uint32_t bf[4][2];
#pragma unroll
            for (int j = 0; j < 4; j++) {
                int nb = wn + j * 8 + fr;
                bf[j][0] = Bb[(kk + fc) * 72 + nb];
                bf[j][1] = Bb[(kk + fc + 4) * 72 + nb];
            }
#pragma unroll
            for (int i = 0; i < 2; i++)
#pragma unroll
                for (int j = 0; j < 4; j++)
                    mma_tf32(acc[i][j][0], acc[i][j][1], acc[i][j][2], acc[i][j][3],
                             af[i][0], af[i][1], af[i][2], af[i][3],
                             bf[j][0], bf[j][1]);
        }
    }

#pragma unroll
    for (int i = 0; i < 2; i++) {
#pragma unroll
        for (int j = 0; j < 4; j++) {
            int row = m0 + wm + i * 16 + fr;
            int col = wn + j * 8 + fc * 2;
            if (row < M)
                *reinterpret_cast<__half2*>(&g_XWH[(size_t)row * HID + col]) =
                    __floats2half2_rn(acc[i][j][0], acc[i][j][1]);
            if (row + 8 < M)
                *reinterpret_cast<__half2*>(&g_XWH[(size_t)(row + 8) * HID + col]) =
                    __floats2half2_rn(acc[i][j][2], acc[i][j][3]);
        }
    }
}

// ---------------------------------------------------------------------------
// Gather: warp per node (R13 shape), packed int4 edge loads, fp32 AGG output.
// Lane owns channels {2l, 2l+1}. AGG[v] = sn*XW[v] + sum w_e * XW[src_e].
// ---------------------------------------------------------------------------

__global__ void gather_kernel(int N) {
    int gid = blockIdx.x * blockDim.x + threadIdx.x;
    int v = gid >> 5;
    int lane = gid & 31;
    if (v >= N) return;

    const __half2* XH2 = reinterpret_cast<const __half2*>(g_XWH);

    int beg = g_ROWPTR[v];
    int end = g_ROWPTR[v + 1];
    float dn = g_DINV[v];
    float sn = dn * dn;

    float2 self = __half22float2(XH2[v * 32 + lane]);
    float a0 = self.x * sn;
    float a1 = self.y * sn;

    int j = beg;
    if ((j & 1) && j < end) {
        int2 p = g_EPK[j];
        float2 x = __half22float2(XH2[p.x * 32 + lane]);
        float w = __int_as_float(p.y);
        a0 = fmaf(w, x.x, a0);
        a1 = fmaf(w, x.y, a1);
        j++;
    }
    for (; j + 3 < end; j += 4) {
        int4 pA = *reinterpret_cast<const int4*>(&g_EPK[j]);
        int4 pB = *reinterpret_cast<const int4*>(&g_EPK[j + 2]);
        float w0 = __int_as_float(pA.y);
        float w1 = __int_as_float(pA.w);
        float w2 = __int_as_float(pB.y);
        float w3 = __int_as_float(pB.w);
        float2 x0 = __half22float2(XH2[pA.x * 32 + lane]);
        float2 x1 = __half22float2(XH2[pA.z * 32 + lane]);
        float2 x2 = __half22float2(XH2[pB.x * 32 + lane]);
        float2 x3 = __half22float2(XH2[pB.z * 32 + lane]);
        a0 = fmaf(w0, x0.x, a0);
        a1 = fmaf(w0, x0.y, a1);
        a0 = fmaf(w1, x1.x, a0);
        a1 = fmaf(w1, x1.y, a1);
        a0 = fmaf(w2, x2.x, a0);
        a1 = fmaf(w2, x2.y, a1);
        a0 = fmaf(w3, x3.x, a0);
        a1 = fmaf(w3, x3.y, a1);
    }
    for (; j < end; ++j) {
        int2 p = g_EPK[j];
        float2 x = __half22float2(XH2[p.x * 32 + lane]);
        float w = __int_as_float(p.y);
        a0 = fmaf(w, x.x, a0);
        a1 = fmaf(w, x.y, a1);
    }

    *reinterpret_cast<float2*>(&g_AGG[v * HID + 2 * lane]) = make_float2(a0, a1);
}

// ---------------------------------------------------------------------------
// BN stats + finalize fused (256 blocks, deterministic last-block ticket)
// ---------------------------------------------------------------------------

__global__ void bn_stats_fin_kernel(const float* __restrict__ gamma,
                                    const float* __restrict__ beta,
                                    const float* __restrict__ lw,
                                    int layer, int L, int N) {
    __shared__ float4 ssum[256];
    __shared__ float4 ssq[256];
    __shared__ unsigned int sIsLast;
    const float4* AGG4 = reinterpret_cast<const float4*>(g_AGG);
    int t = threadIdx.x;
    int stride = gridDim.x * blockDim.x;
    int total = N * 16;
    float4 s = make_float4(0.f, 0.f, 0.f, 0.f);
    float4 q = make_float4(0.f, 0.f, 0.f, 0.f);
    for (int i = blockIdx.x * blockDim.x + t; i < total; i += stride) {
        float4 v = AGG4[i];
        s.x += v.x; s.y += v.y; s.z += v.z; s.w += v.w;
        q.x += v.x * v.x; q.y += v.y * v.y; q.z += v.z * v.z; q.w += v.w * v.w;
    }
    ssum[t] = s;
    ssq[t] = q;
    __syncthreads();
    for (int off = 128; off >= 16; off >>= 1) {
        if (t < off) {
            float4 a = ssum[t], b = ssum[t + off];
            ssum[t] = make_float4(a.x + b.x, a.y + b.y, a.z + b.z, a.w + b.w);
            float4 c = ssq[t], d = ssq[t + off];
            ssq[t] = make_float4(c.x + d.x, c.y + d.y, c.z + d.z, c.w + d.w);
        }
        __syncthreads();
    }
    if (t < 16) {
        *reinterpret_cast<float4*>(&g_PART[blockIdx.x * 128 + t * 4]) = ssum[t];
        *reinterpret_cast<float4*>(&g_PART[blockIdx.x * 128 + 64 + t * 4]) = ssq[t];
    }
    __threadfence();
    __syncthreads();
    if (t == 0)
        sIsLast = (atomicAdd(&g_TICKET, 1u) == (unsigned)gridDim.x - 1u) ? 1u : 0u;
    __syncthreads();
    if (!sIsLast) return;

    if (t == 0) g_TICKET = 0;
    int c = t & 63;
    int g0 = t >> 6;
    float fs = 0.f, fq = 0.f;
    for (int g = g0; g < STATS_BLOCKS; g += 4) {
        fs += g_PART[g * 128 + c];
        fq += g_PART[g * 128 + 64 + c];
    }
    __syncthreads();
    float* s_s = reinterpret_cast<float*>(ssum);
    float* s_q = reinterpret_cast<float*>(ssq);
    s_s[t] = fs;
    s_q[t] = fq;
    __syncthreads();
    if (t < 128) { s_s[t] += s_s[t + 128]; s_q[t] += s_q[t + 128]; }
    __syncthreads();
    if (t < 64) {
        float S = s_s[t] + s_s[t + 64];
        float Q = s_q[t] + s_q[t + 64];
        float invN = 1.0f / (float)N;
        float mean = S * invN;
        float var = Q * invN - mean * mean;
        float inv = rsqrtf(var + 1e-5f);
        float sc = gamma[layer * HID + c] * inv;
        g_SS[c] = sc;
        g_SS[64 + c] = beta[layer * HID + c] - mean * sc;
    }
    if (t == 0) {
        float se = 0.f;
        for (int j = 0; j < L; j++) se += expf(lw[j]);
        g_SS[128] = expf(lw[layer]) / se;
    }
}

// ---------------------------------------------------------------------------
// Normalize + ReLU + residual + softmax-weighted emb accumulation.
// ---------------------------------------------------------------------------

__global__ void bn_norm_kernel(float4* __restrict__ EMB4, int N, int layer, int store_out) {
    const float4* AGG4  = reinterpret_cast<const float4*>(g_AGG);
    const float4* PREV4 = reinterpret_cast<const float4*>((layer & 1) ? g_OUT0 : g_OUT1);
    float4* OUT4        = reinterpret_cast<float4*>((layer & 1) ? g_OUT1 : g_OUT0);

    int t0 = blockIdx.x * blockDim.x + threadIdx.x;
    int c4 = (t0 & 15) * 4;
    float4 sc = *reinterpret_cast<const float4*>(&g_SS[c4]);
    float4 sh = *reinterpret_cast<const float4*>(&g_SS[64 + c4]);
    float w = g_SS[128];
    int total = N * 16;
    int stride = gridDim.x * blockDim.x;
    for (int i = t0; i < total; i += stride) {
        float4 v = AGG4[i];
        float4 o;
        o.x = fmaxf(fmaf(v.x, sc.x, sh.x), 0.f);
        o.y = fmaxf(fmaf(v.y, sc.y, sh.y), 0.f);
        o.z = fmaxf(fmaf(v.z, sc.z, sh.z), 0.f);
        o.w = fmaxf(fmaf(v.w, sc.w, sh.w), 0.f);
        if (layer > 0) {
            float4 p = PREV4[i];
            o.x = fmaf(0.7f, p.x, o.x);
            o.y = fmaf(0.7f, p.y, o.y);
            o.z = fmaf(0.7f, p.z, o.z);
            o.w = fmaf(0.7f, p.w, o.w);
        }
        if (store_out) OUT4[i] = o;
        if (layer == 0) {
            EMB4[i] = make_float4(w * o.x, w * o.y, w * o.z, w * o.w);
        } else {
            float4 e = EMB4[i];
            e.x = fmaf(w, o.x, e.x);
            e.y = fmaf(w, o.y, e.y);
            e.z = fmaf(w, o.z, e.z);
            e.w = fmaf(w, o.w, e.w);
            EMB4[i] = e;
        }
    }
}

// ---------------------------------------------------------------------------
// Host launcher — kernel launches + one deterministic attribute call.
// NS=4 (59.4KB dyn smem) preferred; NS=3 (44.5KB, no opt-in) fallback.
// ---------------------------------------------------------------------------

#define SMEM_NS4 (4 * (A_ST + B_ST) * 4)
#define SMEM_NS3 (3 * (A_ST + B_ST) * 4)

extern "C" void kernel_launch(void* const* d_in, const int* in_sizes, int n_in,
                              void* d_out, int out_size) {
    const float* feat  = (const float*)d_in[0];
    const int* ewords  = (const int*)d_in[1];
    const float* W0    = (const float*)d_in[2];
    const float* Wh    = (const float*)d_in[4];
    const float* gamma = (const float*)d_in[6];
    const float* beta  = (const float*)d_in[7];
    const float* lw    = (const float*)d_in[8];
    float* out         = (float*)d_out;

    int hid    = in_sizes[3];
    int in_dim = in_sizes[2] / hid;
    int N      = in_sizes[0] / in_dim;
    int E      = in_sizes[1] / 2;
    int L      = in_sizes[8];

    int nb = (N + SBS - 1) / SBS;
    int gemm_blocks = (N + 127) / 128;
    int gather_blocks = (N * 32 + 255) / 256;   // warp per node

    // Deterministic every call; choose NS=4 iff opt-in succeeds.
    cudaError_t aerr = cudaFuncSetAttribute(
        gemm_tf32_kernel<4>, cudaFuncAttributeMaxDynamicSharedMemorySize, SMEM_NS4);
    bool use4 = (aerr == cudaSuccess);
    if (!use4) (void)cudaGetLastError();    // clear sticky error

    auto launch_gemm = [&](const float* A0, int sel, const float* W, int M, int K) {
        if (use4)
            gemm_tf32_kernel<4><<<gemm_blocks, 256, SMEM_NS4>>>(A0, sel, W, M, K);
        else
            gemm_tf32_kernel<3><<<gemm_blocks, 256, SMEM_NS3>>>(A0, sel, W, M, K);
    };

    init_detect_kernel<<<(N + 255) / 256, 256>>>(ewords, N, E);              // 1
    count_kernel<<<(E + 255) / 256, 256>>>(ewords, E);                       // 2
    scan1_kernel<<<nb, SBS>>>(N);                                            // 3 (+dinv)
    launch_gemm(feat, 0, W0, N, in_dim);                                     // 4 (profiled)
    scan2_kernel<<<1, SBS>>>(nb);                                            // 5
    scan3_kernel<<<(N + 255) / 256, 256>>>(N, E);                            // 6
    fill_kernel<<<(E + 255) / 256, 256>>>(ewords, E);                        // 7

    for (int layer = 0; layer < L; layer++) {
        if (layer > 0) {
            int src_sel = ((layer - 1) & 1) ? 2 : 1;
            const float* W = Wh + (size_t)(layer - 1) * hid * hid;
            launch_gemm(feat, src_sel, W, N, hid);
        }
        gather_kernel<<<gather_blocks, 256>>>(N);
        bn_stats_fin_kernel<<<STATS_BLOCKS, 256>>>(gamma, beta, lw, layer, L, N);
        bn_norm_kernel<<<512, 256>>>((float4*)out, N, layer, layer < L - 1 ? 1 : 0);
    }
}